// round 9
// baseline (speedup 1.0000x reference)
#include <cuda_runtime.h>
#include <cuda_fp16.h>
#include <cstdint>

// Problem constants
#define B_      4
#define C_IN_   32
#define C_OUT_  64
#define E_      200000
#define KK_     5
#define CKDIM   160
#define TILE_M  128
#define NTHR    512
#define NCH     20             // 16B chunks per row (160 fp16 k-values)

#define TILES_PER_B  1563
#define TOTAL_TILES  (B_ * TILES_PER_B)   // 6252
#define NCTA         148

// SMEM byte offsets
#define SM_BH    0             // W fp16 panel: 64 x 320B = 20480
#define SM_A0    20480         // A fp16 panel buf0: 128 x 320B = 40960
#define SM_A1    61440         // A fp16 panel buf1
#define SM_OUT   102400        // 64 x 132 x 4B = 33792 (epilogue staging)
#define SM_CTRL  136192
#define SM_TOTAL 136208

#define OUT_PITCH 132

// Global scratch
__device__ __align__(128) float g_xT[(size_t)B_ * E_ * C_IN_];   // (B,E,C)
__device__ __align__(128) unsigned char g_Bh[20480];             // W fp16 panel
__device__ int g_ctr;

// ---------------------------------------------------------------------------
// helpers
// ---------------------------------------------------------------------------
__device__ __forceinline__ uint32_t smem_u32(const void* p) {
    uint32_t a;
    asm("{ .reg .u64 t; cvta.to.shared.u64 t, %1; cvt.u32.u64 %0, t; }" : "=r"(a) : "l"(p));
    return a;
}
__device__ __forceinline__ int swzc(int kc, int row) {
    return (kc < 16) ? (kc ^ (row & 7)) : (16 + ((kc - 16) ^ (row & 3)));
}
__device__ __forceinline__ void ldm_x4(uint32_t* r, uint32_t addr) {
    asm volatile("ldmatrix.sync.aligned.m8n8.x4.shared.b16 {%0,%1,%2,%3}, [%4];"
        : "=r"(r[0]), "=r"(r[1]), "=r"(r[2]), "=r"(r[3]) : "r"(addr));
}
__device__ __forceinline__ void mma16816(float* d, const uint32_t* a, const uint32_t* b) {
    asm volatile(
        "mma.sync.aligned.m16n8k16.row.col.f32.f16.f16.f32 "
        "{%0,%1,%2,%3}, {%4,%5,%6,%7}, {%8,%9}, {%0,%1,%2,%3};"
        : "+f"(d[0]), "+f"(d[1]), "+f"(d[2]), "+f"(d[3])
        : "r"(a[0]), "r"(a[1]), "r"(a[2]), "r"(a[3]), "r"(b[0]), "r"(b[1]));
}
__device__ __forceinline__ uint32_t pack_half2(float g0, float g1) {
    __half2 h = __floats2half2_rn(g0, g1);
    return *reinterpret_cast<uint32_t*>(&h);
}

// ---------------------------------------------------------------------------
// Kernel 1: transpose x (B,C,E) -> g_xT (B,E,C)
// ---------------------------------------------------------------------------
__global__ void __launch_bounds__(256) transpose_x(const float* __restrict__ x) {
    __shared__ float tile[32][33];
    const int b  = blockIdx.y;
    const int e0 = blockIdx.x * 32;
    const int tx = threadIdx.x & 31;
    const int ty = threadIdx.x >> 5;
    #pragma unroll
    for (int i = 0; i < 4; i++) {
        const int c = ty + i * 8;
        tile[c][tx] = x[((size_t)b * C_IN_ + c) * E_ + e0 + tx];
    }
    __syncthreads();
    #pragma unroll
    for (int i = 0; i < 4; i++) {
        const int e = ty + i * 8;
        g_xT[((size_t)b * E_ + e0 + e) * C_IN_ + tx] = tile[tx][e];
    }
}

// ---------------------------------------------------------------------------
// Kernel 2: W -> fp16 panel, remap k = j*32 + c; reset tile counter.
// ---------------------------------------------------------------------------
__global__ void __launch_bounds__(512) prep_W(const float* __restrict__ W) {
    if (threadIdx.x == 0) g_ctr = 0;
    for (int i = threadIdx.x; i < C_OUT_ * CKDIM; i += 512) {
        const int o   = i / CKDIM;
        const int rem = i - o * CKDIM;
        const int c   = rem / KK_;
        const int j   = rem - c * KK_;
        const int k   = j * 32 + c;
        const int kc  = k >> 3;
        const int ki  = k & 7;
        const uint32_t off = (uint32_t)((o * NCH + swzc(kc, o)) * 16 + ki * 2);
        *reinterpret_cast<__half*>(g_Bh + off) = __float2half_rn(W[i]);
    }
}

// ---------------------------------------------------------------------------
// Kernel 3: persistent gather(LDG->regs) + combine + fp16 HMMA + epilogue.
//   2 syncs per tile; A panel double-buffered; no raw staging.
// ---------------------------------------------------------------------------
__global__ void __launch_bounds__(NTHR)
meshconv_kernel(const int*   __restrict__ Gi,
                const float* __restrict__ bias,
                float*       __restrict__ out) {
    extern __shared__ __align__(1024) unsigned char smem[];
    const uint32_t sbase = smem_u32(smem);
    int* s_next = (int*)(smem + SM_CTRL);
    float* s_out = (float*)(smem + SM_OUT);

    const int t     = threadIdx.x;
    const int w     = t >> 5;
    const int l     = t & 31;
    const int e_loc = t >> 2;      // 0..127 : edge within tile
    const int quad  = t & 3;       // 8-channel group

    // --- W panel once per CTA -----------------------------------------------
    {
        const uint4* src = (const uint4*)g_Bh;
        uint4* dst = (uint4*)smem;
        #pragma unroll
        for (int i = 0; i < 3; i++) {
            const int idx = t + i * NTHR;
            if (idx < 1280) dst[idx] = src[idx];
        }
    }

    // --- GEMM geometry + hoisted bias ---------------------------------------
    const int wm = w & 7, wn = w >> 3;
    const int m0 = wm * 16, n0 = wn * 32;
    const int mrA   = m0 + ((l >> 3) & 1) * 8 + (l & 7);
    const int kselA = (l >> 4);
    const int nrB   = ((l >> 4) & 1) * 8 + (l & 7);
    const int kselB = ((l >> 3) & 1);
    float bn[4][2];
    #pragma unroll
    for (int nb = 0; nb < 4; nb++) {
        const int n = n0 + nb * 8 + (l & 3) * 2;
        bn[nb][0] = __ldg(&bias[n]);
        bn[nb][1] = __ldg(&bias[n + 1]);
    }

    auto grab = [&](void) { if (t == 0) *s_next = atomicAdd(&g_ctr, 1); };

    int idx5[KK_];
    float f[KK_][8];

    auto gi_load = [&](int tile) {
        const int b = tile / TILES_PER_B;
        const int e = (tile - b * TILES_PER_B) * TILE_M + e_loc;
        const int* gp = Gi + ((size_t)b * E_ + e) * KK_;
        const bool ok = (e < E_);
        #pragma unroll
        for (int j = 0; j < KK_; j++) idx5[j] = ok ? gp[j] : 0;
    };
    auto gather_ldg = [&](int tile) {
        const int b = tile / TILES_PER_B;
        const float* xb = g_xT + (size_t)b * E_ * C_IN_ + quad * 8;
        #pragma unroll
        for (int j = 0; j < KK_; j++) {
            const float4* p = (const float4*)(xb + (size_t)idx5[j] * C_IN_);
            const float4 lo = p[0];
            const float4 hi = p[1];
            f[j][0] = lo.x; f[j][1] = lo.y; f[j][2] = lo.z; f[j][3] = lo.w;
            f[j][4] = hi.x; f[j][5] = hi.y; f[j][6] = hi.z; f[j][7] = hi.w;
        }
    };
    auto combine = [&](uint32_t abase) {
        #pragma unroll
        for (int j = 0; j < KK_; j++) {
            float g[8];
            #pragma unroll
            for (int ci = 0; ci < 8; ci++) {
                const float f0 = f[0][ci], f1 = f[1][ci], f2 = f[2][ci],
                            f3 = f[3][ci], f4 = f[4][ci];
                switch (j) {
                    case 0: g[ci] = f0; break;
                    case 1: g[ci] = f1 + f3; break;
                    case 2: g[ci] = f2 + f4; break;
                    case 3: g[ci] = fabsf(f1 - f3); break;
                    default: g[ci] = fabsf(f2 - f4); break;
                }
            }
            uint4 h4;
            uint32_t* hp = (uint32_t*)&h4;
            #pragma unroll
            for (int p = 0; p < 4; p++) hp[p] = pack_half2(g[2 * p], g[2 * p + 1]);
            const int kc = j * 4 + quad;
            const uint32_t off = (uint32_t)((e_loc * NCH + swzc(kc, e_loc)) * 16);
            *(uint4*)(smem + abase + off) = h4;
        }
    };
    auto gemm_stage = [&](uint32_t abase) {
        float acc[4][4] = {{0.f}};
        #pragma unroll
        for (int ks = 0; ks < 10; ks++) {
            const int kc0 = ks * 2;
            uint32_t a4[4], b0[4], b1[4];
            {
                const int kc = kc0 + kselA;
                ldm_x4(a4, sbase + abase + (uint32_t)((mrA * NCH + swzc(kc, mrA)) * 16));
            }
            {
                const int kc = kc0 + kselB;
                const int r0 = n0 + nrB;
                const int r1 = n0 + 16 + nrB;
                ldm_x4(b0, sbase + SM_BH + (uint32_t)((r0 * NCH + swzc(kc, r0)) * 16));
                ldm_x4(b1, sbase + SM_BH + (uint32_t)((r1 * NCH + swzc(kc, r1)) * 16));
            }
            mma16816(acc[0], a4, b0);     mma16816(acc[1], a4, b0 + 2);
            mma16816(acc[2], a4, b1);     mma16816(acc[3], a4, b1 + 2);
        }
        const int r = m0 + (l >> 2);
        #pragma unroll
        for (int nb = 0; nb < 4; nb++) {
            const int n = n0 + nb * 8 + (l & 3) * 2;
            s_out[n * OUT_PITCH + r]           = acc[nb][0] + bn[nb][0];
            s_out[(n + 1) * OUT_PITCH + r]     = acc[nb][1] + bn[nb][1];
            s_out[n * OUT_PITCH + r + 8]       = acc[nb][2] + bn[nb][0];
            s_out[(n + 1) * OUT_PITCH + r + 8] = acc[nb][3] + bn[nb][1];
        }
    };
    auto sout_store = [&](int tile) {
        const int b = tile / TILES_PER_B;
        const int e_base = (tile - b * TILES_PER_B) * TILE_M;
        const int o     = t >> 3;
        const int chunk = t & 7;
        if (e_base + chunk * 16 < E_) {
            float* orow = out + ((size_t)(b * C_OUT_ + o)) * E_ + e_base;
            const float* srow = s_out + o * OUT_PITCH + chunk * 16;
            #pragma unroll
            for (int i = 0; i < 4; i++) {
                float4 v = make_float4(srow[i * 4 + 0], srow[i * 4 + 1],
                                       srow[i * 4 + 2], srow[i * 4 + 3]);
                *(float4*)(orow + chunk * 16 + i * 4) = v;
            }
        }
    };

    // --- prologue ------------------------------------------------------------
    grab();
    __syncthreads();
    int cur = *s_next;              // every CTA gets >=1 tile (6252 > 148)
    gi_load(cur);
    gather_ldg(cur);
    grab();
    combine(SM_A0);
    __syncthreads();                // A0 ready; s_next visible
    int nxt = *s_next;
    if (nxt < TOTAL_TILES) gi_load(nxt);
    uint32_t abase = SM_A0, abase_alt = SM_A1;

    // --- main loop: 2 syncs per tile ----------------------------------------
    for (;;) {
        const bool have = (nxt < TOTAL_TILES);
        if (have) gather_ldg(nxt);          // LDG latency hidden under GEMM
        grab();
        gemm_stage(abase);                  // MMA + stage s_out(+bias)
        __syncthreads();                    // SYNC_1: s_out ready; s_next ready
        sout_store(cur);                    // STG overlaps combine below
        if (!have) break;
        combine(abase_alt);                 // regs -> A[p^1]
        const int nnxt = *s_next;
        if (nnxt < TOTAL_TILES) gi_load(nnxt);
        __syncthreads();                    // SYNC_2: A[p^1] ready; s_out free
        cur = nxt; nxt = nnxt;
        const uint32_t tmp = abase; abase = abase_alt; abase_alt = tmp;
    }
}

// ---------------------------------------------------------------------------
extern "C" void kernel_launch(void* const* d_in, const int* in_sizes, int n_in,
                              void* d_out, int out_size) {
    const float* x    = (const float*)d_in[0];
    const int*   Gi   = (const int*)  d_in[1];
    const float* W    = (const float*)d_in[2];
    const float* bias = (const float*)d_in[3];
    float*       out  = (float*)d_out;

    transpose_x<<<dim3(E_ / 32, B_), 256>>>(x);
    prep_W<<<1, 512>>>(W);

    cudaFuncSetAttribute(meshconv_kernel,
                         cudaFuncAttributeMaxDynamicSharedMemorySize, SM_TOTAL);
    meshconv_kernel<<<NCTA, NTHR, SM_TOTAL>>>(Gi, bias, out);
}

// round 10
// speedup vs baseline: 1.1324x; 1.1324x over previous
#include <cuda_runtime.h>
#include <cuda_fp16.h>
#include <cstdint>

// Problem constants
#define B_      4
#define C_IN_   32
#define C_OUT_  64
#define E_      200000
#define KK_     5
#define CKDIM   160
#define TILE_M  128
#define NTHR    512
#define NCH     20             // 16B chunks per row (160 fp16 k-values)

#define TILES_PER_B  1563
#define TOTAL_TILES  (B_ * TILES_PER_B)   // 6252
#define NCTA         148

// SMEM byte offsets
#define SM_BH    0             // W fp16 panel: 64 x 320B = 20480
#define SM_A     20480         // A fp16 panel: 128 x 320B = 40960
#define SM_RAW   61440         // 640 lines x 128B = 81920
#define SM_OUT   143360        // 64 x 132 x 4B = 33792
#define SM_CTRL  177152
#define SM_TOTAL 177168

#define OUT_PITCH 132

// Global scratch
__device__ __align__(128) float g_xT[(size_t)B_ * E_ * C_IN_];   // (B,E,C)
__device__ int g_ctr;

// ---------------------------------------------------------------------------
// helpers
// ---------------------------------------------------------------------------
__device__ __forceinline__ uint32_t smem_u32(const void* p) {
    uint32_t a;
    asm("{ .reg .u64 t; cvta.to.shared.u64 t, %1; cvt.u32.u64 %0, t; }" : "=r"(a) : "l"(p));
    return a;
}
__device__ __forceinline__ int swzc(int kc, int row) {
    return (kc < 16) ? (kc ^ (row & 7)) : (16 + ((kc - 16) ^ (row & 3)));
}
__device__ __forceinline__ void ldm_x4(uint32_t* r, uint32_t addr) {
    asm volatile("ldmatrix.sync.aligned.m8n8.x4.shared.b16 {%0,%1,%2,%3}, [%4];"
        : "=r"(r[0]), "=r"(r[1]), "=r"(r[2]), "=r"(r[3]) : "r"(addr));
}
__device__ __forceinline__ void mma16816(float* d, const uint32_t* a, const uint32_t* b) {
    asm volatile(
        "mma.sync.aligned.m16n8k16.row.col.f32.f16.f16.f32 "
        "{%0,%1,%2,%3}, {%4,%5,%6,%7}, {%8,%9}, {%0,%1,%2,%3};"
        : "+f"(d[0]), "+f"(d[1]), "+f"(d[2]), "+f"(d[3])
        : "r"(a[0]), "r"(a[1]), "r"(a[2]), "r"(a[3]), "r"(b[0]), "r"(b[1]));
}
__device__ __forceinline__ uint32_t pack_half2(float g0, float g1) {
    __half2 h = __floats2half2_rn(g0, g1);
    return *reinterpret_cast<uint32_t*>(&h);
}
__device__ __forceinline__ void cp_async16(uint32_t smem_addr, const void* gptr) {
    asm volatile("cp.async.cg.shared.global [%0], [%1], 16;"
                 :: "r"(smem_addr), "l"(gptr) : "memory");
}

// ---------------------------------------------------------------------------
// Kernel 1: transpose x (B,C,E) -> g_xT (B,E,C); block(0,0) resets counter.
// ---------------------------------------------------------------------------
__global__ void __launch_bounds__(256) transpose_x(const float* __restrict__ x) {
    if (blockIdx.x == 0 && blockIdx.y == 0 && threadIdx.x == 0) g_ctr = 0;
    __shared__ float tile[32][33];
    const int b  = blockIdx.y;
    const int e0 = blockIdx.x * 32;
    const int tx = threadIdx.x & 31;
    const int ty = threadIdx.x >> 5;
    #pragma unroll
    for (int i = 0; i < 4; i++) {
        const int c = ty + i * 8;
        tile[c][tx] = x[((size_t)b * C_IN_ + c) * E_ + e0 + tx];
    }
    __syncthreads();
    #pragma unroll
    for (int i = 0; i < 4; i++) {
        const int e = ty + i * 8;
        g_xT[((size_t)b * E_ + e0 + e) * C_IN_ + tx] = tile[tx][e];
    }
}

// ---------------------------------------------------------------------------
struct TileCtx { int b, e_base, valid; };
__device__ __forceinline__ TileCtx decode_tile(int tile) {
    TileCtx tc;
    tc.b = tile / TILES_PER_B;
    const int r = tile - tc.b * TILES_PER_B;
    tc.e_base = r * TILE_M;
    tc.valid  = (E_ - tc.e_base) * KK_;
    return tc;
}

// ---------------------------------------------------------------------------
// Kernel 2: persistent fused gather(cp.async) + combine + fp16 HMMA + epilogue.
//   16 warps = 4 m-groups x 4 n-groups; B fragments held in registers.
// ---------------------------------------------------------------------------
__global__ void __launch_bounds__(NTHR, 1)
meshconv_kernel(const int*   __restrict__ Gi,
                const float* __restrict__ W,
                const float* __restrict__ bias,
                float*       __restrict__ out) {
    extern __shared__ __align__(1024) unsigned char smem[];
    const uint32_t sbase = smem_u32(smem);
    int* s_next = (int*)(smem + SM_CTRL);
    float* s_out = (float*)(smem + SM_OUT);

    const int t   = threadIdx.x;
    const int w   = t >> 5;
    const int l   = t & 31;
    const int sub = (l >> 3);
    const int seg = l & 7;

    // --- W fp16 panel built per CTA from global W (L2-hot, once) ------------
    #pragma unroll
    for (int r = 0; r < 20; r++) {
        const int i   = t + r * NTHR;          // 0..10239
        const int o   = i / CKDIM;
        const int rem = i - o * CKDIM;
        const int c   = rem / KK_;
        const int j   = rem - c * KK_;
        const int k   = j * 32 + c;
        const int kc  = k >> 3;
        const int ki  = k & 7;
        const uint32_t off = (uint32_t)((o * NCH + swzc(kc, o)) * 16 + ki * 2);
        *reinterpret_cast<__half*>(smem + SM_BH + off) = __float2half_rn(W[i]);
    }

    // --- GEMM geometry: warp = 32m x 16n ------------------------------------
    const int m0 = (w & 3) * 32;
    const int n0 = (w >> 2) * 16;
    const int mrA   = ((l >> 3) & 1) * 8 + (l & 7);   // + m0 (+16 for hi)
    const int kselA = (l >> 4);
    const int nrB   = ((l >> 4) & 1) * 8 + (l & 7);
    const int kselB = ((l >> 3) & 1);
    float bn[2][2];
    #pragma unroll
    for (int g = 0; g < 2; g++) {
        const int n = n0 + g * 8 + (l & 3) * 2;
        bn[g][0] = __ldg(&bias[n]);
        bn[g][1] = __ldg(&bias[n + 1]);
    }

    auto grab = [&](void) { if (t == 0) *s_next = atomicAdd(&g_ctr, 1); };

    grab();
    __syncthreads();                 // W panel visible; s_next ready
    int cur = *s_next;               // every CTA gets >= 1 tile

    // --- B fragments: load once into registers (40 regs) --------------------
    uint32_t Breg[10][4];
    #pragma unroll
    for (int ks = 0; ks < 10; ks++) {
        const int kc  = ks * 2 + kselB;
        const int row = n0 + nrB;
        ldm_x4(Breg[ks], sbase + SM_BH + (uint32_t)((row * NCH + swzc(kc, row)) * 16));
    }

    int gi[10];
    auto gi_load = [&](int tile) {
        const TileCtx tc = decode_tile(tile);
        const int* GiB = Gi + (size_t)tc.b * E_ * KK_ + (size_t)tc.e_base * KK_;
        #pragma unroll
        for (int i = 0; i < 10; i++) {
            const int line = (w * 4 + sub) + i * 64;
            gi[i] = (line < tc.valid) ? GiB[line] : 0;
        }
    };
    auto gather_issue = [&](int tile) {
        const TileCtx tc = decode_tile(tile);
        const float* xb = g_xT + (size_t)tc.b * E_ * C_IN_;
        #pragma unroll
        for (int i = 0; i < 10; i++) {
            const int line  = (w * 4 + sub) + i * 64;
            const int chunk = seg ^ (line & 7);
            cp_async16(sbase + SM_RAW + (uint32_t)(line * 128 + chunk * 16),
                       xb + (size_t)gi[i] * C_IN_ + seg * 4);
        }
        asm volatile("cp.async.commit_group;" ::: "memory");
    };
    auto combine = [&](void) {
        const float4* sRaw4 = (const float4*)(smem + SM_RAW);
        const int e_loc = t >> 2;
        const int quad  = t & 3;
        float f[KK_][8];
        #pragma unroll
        for (int j = 0; j < KK_; j++) {
            const int row = e_loc * KK_ + j;
            #pragma unroll
            for (int q = 0; q < 2; q++) {
                const int chunk = (quad * 2 + q) ^ (row & 7);
                const float4 tmp = sRaw4[row * 8 + chunk];
                f[j][q * 4 + 0] = tmp.x; f[j][q * 4 + 1] = tmp.y;
                f[j][q * 4 + 2] = tmp.z; f[j][q * 4 + 3] = tmp.w;
            }
        }
        #pragma unroll
        for (int j = 0; j < KK_; j++) {
            float g[8];
            #pragma unroll
            for (int ci = 0; ci < 8; ci++) {
                const float f0 = f[0][ci], f1 = f[1][ci], f2 = f[2][ci],
                            f3 = f[3][ci], f4 = f[4][ci];
                switch (j) {
                    case 0: g[ci] = f0; break;
                    case 1: g[ci] = f1 + f3; break;
                    case 2: g[ci] = f2 + f4; break;
                    case 3: g[ci] = fabsf(f1 - f3); break;
                    default: g[ci] = fabsf(f2 - f4); break;
                }
            }
            uint4 h4;
            uint32_t* hp = (uint32_t*)&h4;
            #pragma unroll
            for (int p = 0; p < 4; p++) hp[p] = pack_half2(g[2 * p], g[2 * p + 1]);
            const int kc = j * 4 + quad;
            const uint32_t off = (uint32_t)((e_loc * NCH + swzc(kc, e_loc)) * 16);
            *(uint4*)(smem + SM_A + off) = h4;
        }
    };
    auto gemm_epilogue = [&](int tile) {
        float acc[4][4] = {{0.f}};
        #pragma unroll
        for (int ks = 0; ks < 10; ks++) {
            const int kc = ks * 2 + kselA;
            uint32_t alo[4], ahi[4];
            {
                const int rl = m0 + mrA;
                const int rh = m0 + 16 + mrA;
                ldm_x4(alo, sbase + SM_A + (uint32_t)((rl * NCH + swzc(kc, rl)) * 16));
                ldm_x4(ahi, sbase + SM_A + (uint32_t)((rh * NCH + swzc(kc, rh)) * 16));
            }
            mma16816(acc[0], alo, Breg[ks]);       // rows m0..15,  cols n0..7
            mma16816(acc[1], alo, Breg[ks] + 2);   // rows m0..15,  cols n0+8..15
            mma16816(acc[2], ahi, Breg[ks]);       // rows m0+16..31, n0..7
            mma16816(acc[3], ahi, Breg[ks] + 2);   // rows m0+16..31, n0+8..15
        }
        // stage into s_out[o][e] (+bias), conflict-free banks
        const TileCtx tc = decode_tile(tile);
        const int r  = m0 + (l >> 2);
        #pragma unroll
        for (int g = 0; g < 2; g++) {              // n-block within warp tile
            const int n = n0 + g * 8 + (l & 3) * 2;
            const float* a0 = acc[g];              // rows r, r+8
            const float* a1 = acc[2 + g];          // rows r+16, r+24
            s_out[n * OUT_PITCH + r]            = a0[0] + bn[g][0];
            s_out[(n + 1) * OUT_PITCH + r]      = a0[1] + bn[g][1];
            s_out[n * OUT_PITCH + r + 8]        = a0[2] + bn[g][0];
            s_out[(n + 1) * OUT_PITCH + r + 8]  = a0[3] + bn[g][1];
            s_out[n * OUT_PITCH + r + 16]       = a1[0] + bn[g][0];
            s_out[(n + 1) * OUT_PITCH + r + 16] = a1[1] + bn[g][1];
            s_out[n * OUT_PITCH + r + 24]       = a1[2] + bn[g][0];
            s_out[(n + 1) * OUT_PITCH + r + 24] = a1[3] + bn[g][1];
        }
        __syncthreads();
        // coalesced float4 stores
        {
            const int o     = t >> 3;
            const int chunk = t & 7;
            if (tc.e_base + chunk * 16 < E_) {
                float* orow = out + ((size_t)(tc.b * C_OUT_ + o)) * E_ + tc.e_base;
                const float* srow = s_out + o * OUT_PITCH + chunk * 16;
                #pragma unroll
                for (int i = 0; i < 4; i++) {
                    float4 v = make_float4(srow[i * 4 + 0], srow[i * 4 + 1],
                                           srow[i * 4 + 2], srow[i * 4 + 3]);
                    *(float4*)(orow + chunk * 16 + i * 4) = v;
                }
            }
        }
    };

    // --- prologue ------------------------------------------------------------
    gi_load(cur);
    gather_issue(cur);
    asm volatile("cp.async.wait_group 0;" ::: "memory");
    grab();
    __syncthreads();
    int nxt = *s_next;
    combine();
    if (nxt < TOTAL_TILES) gi_load(nxt);
    __syncthreads();

    // --- main pipelined loop -------------------------------------------------
    for (;;) {
        const bool have = (nxt < TOTAL_TILES);
        if (have) gather_issue(nxt);          // overlaps GEMM
        grab();
        gemm_epilogue(cur);                   // contains one sync
        if (!have) break;
        asm volatile("cp.async.wait_group 0;" ::: "memory");
        __syncthreads();                      // raw ready; s_out consumed
        const int nnxt = *s_next;
        if (nnxt < TOTAL_TILES) gi_load(nnxt);
        combine();
        __syncthreads();                      // A panel ready
        cur = nxt;
        nxt = nnxt;
    }
}

// ---------------------------------------------------------------------------
extern "C" void kernel_launch(void* const* d_in, const int* in_sizes, int n_in,
                              void* d_out, int out_size) {
    const float* x    = (const float*)d_in[0];
    const int*   Gi   = (const int*)  d_in[1];
    const float* W    = (const float*)d_in[2];
    const float* bias = (const float*)d_in[3];
    float*       out  = (float*)d_out;

    transpose_x<<<dim3(E_ / 32, B_), 256>>>(x);

    cudaFuncSetAttribute(meshconv_kernel,
                         cudaFuncAttributeMaxDynamicSharedMemorySize, SM_TOTAL);
    meshconv_kernel<<<NCTA, NTHR, SM_TOTAL>>>(Gi, W, bias, out);
}